// round 9
// baseline (speedup 1.0000x reference)
#include <cuda_runtime.h>
#include <cstdint>

// ---------------------------------------------------------------------------
// Smolgen pipeline on GB300 (sm_103a), round 9: all-LDSM tf32 GEMMs, 2 CTAs/SM.
//   prep: round all weights to tf32 (RNA), one fused launch
//   A: flat  = x @ W_tcR^T        (65536 x 32,  K=1024)  BM128/BN32/BK64
//   B: graw4 = flat @ W_gcR^T     split-K x4 partials     BM64/BN128/BK32
//      rmsnorm: gg = norm(sum partials + bias), tf32-rounded
//   C: hr  = gg @ W_headsR^T      (1024 x 4096, K=256)   BM128/BN256/BK32
//   D: out = hr @ W_logitR^T      (16384 x 4096, K=256)  BM128/BN256/BK32
// ---------------------------------------------------------------------------

__device__ float g_flat[1024 * 2048];
__device__ float g_graw4[4 * 1024 * 256];
__device__ float g_g[1024 * 256];
__device__ float g_hr[1024 * 4096];
__device__ float g_WtcR[32 * 1024];
__device__ float g_WgcR[256 * 2048];
__device__ float g_WheadsR[16 * 256 * 256];
__device__ float g_WlogitR[4096 * 256];

__device__ __forceinline__ float round_tf32(float x) {
    float y;
    asm("cvt.rna.tf32.f32 %0, %1;" : "=f"(y) : "f"(x));
    return y;
}
__device__ __forceinline__ uint32_t as_tf32_bits(uint32_t bits) {
    float y;
    asm("cvt.rna.tf32.f32 %0, %1;" : "=f"(y) : "f"(__uint_as_float(bits)));
    return __float_as_uint(y);
}

__device__ __forceinline__ void mma_tf32(float* d, const uint32_t* a, const uint32_t* b) {
    asm volatile(
        "mma.sync.aligned.m16n8k8.row.col.f32.tf32.tf32.f32 "
        "{%0,%1,%2,%3},{%4,%5,%6,%7},{%8,%9},{%0,%1,%2,%3};"
        : "+f"(d[0]), "+f"(d[1]), "+f"(d[2]), "+f"(d[3])
        : "r"(a[0]), "r"(a[1]), "r"(a[2]), "r"(a[3]), "r"(b[0]), "r"(b[1]));
}

__device__ __forceinline__ void ldsm_x4(uint32_t* r, uint32_t addr) {
    asm volatile(
        "ldmatrix.sync.aligned.m8n8.x4.shared.b16 {%0,%1,%2,%3}, [%4];"
        : "=r"(r[0]), "=r"(r[1]), "=r"(r[2]), "=r"(r[3])
        : "r"(addr));
}

__device__ __forceinline__ void cp16(uint32_t saddr, const float* gptr) {
    asm volatile("cp.async.cg.shared.global [%0], [%1], 16;" ::"r"(saddr), "l"(gptr));
}
__device__ __forceinline__ void cp_commit() { asm volatile("cp.async.commit_group;"); }
__device__ __forceinline__ uint32_t smem_u32(const void* p) {
    return (uint32_t)__cvta_generic_to_shared(p);
}

// ======================= LDSM tf32 GEMM (all stages) =========================
// C[.,N] = A[.,lda-rows] @ B[.,lda-rows]^T on a K-extent of Kext, row stride
// lda (floats) for both A and B. blockIdx.z = split-K chunk: A,B advance by
// z*Kext along the row; C advances by z*csplit elements.
// Warp tile = (BM/WARPS_M) x (BN/WARPS_N). Fragments via ldmatrix.x4.
// CVT_A: round A fragments to tf32 post-load (A raw fp32).
// ROUND_OUT: round outputs to tf32 for the next consumer.
template <int BM, int BN, int BK, int WARPS_M, int WARPS_N, bool CVT_A, bool ROUND_OUT>
__global__ void __launch_bounds__(256, 2)
    gemm_ldsm(const float* __restrict__ A, const float* __restrict__ B,
              float* __restrict__ C, int N, int Kext, int lda, long csplit) {
    static_assert(WARPS_M * WARPS_N == 8, "8 warps");
    constexpr int WM_ITER = BM / (WARPS_M * 16);
    constexpr int WN_PAIRS = BN / (WARPS_N * 16);
    constexpr int WN_ITER = 2 * WN_PAIRS;
    static_assert(WM_ITER >= 1 && WN_PAIRS >= 1, "tile split");
    constexpr int LDR = BK + 4;            // +16B per row: conflict-free LDSM
    constexpr int ASZB = BM * LDR * 4;
    constexpr int BSZB = BN * LDR * 4;
    constexpr int SSZB = ASZB + BSZB;
    constexpr int A_LD = BM * (BK / 4) / 256;
    constexpr int B_LD = BN * (BK / 4) / 256;
    static_assert(A_LD * 256 * 4 == BM * BK, "A chunks");
    static_assert(B_LD * 256 * 4 == BN * BK, "B chunks");

    extern __shared__ float smem[];
    const uint32_t sbase = smem_u32(smem);

    const int tid = threadIdx.x;
    const int warp = tid >> 5;
    const int lane = tid & 31;
    const int gid = lane >> 2;
    const int tig = lane & 3;
    const int wm0 = (warp / WARPS_N) * (WM_ITER * 16);
    const int wn0 = (warp % WARPS_N) * (WN_PAIRS * 16);
    const long brow = (long)blockIdx.y * BM;
    const long bcol = (long)blockIdx.x * BN;
    const int NK = Kext / BK;

    // Split-K offsets.
    const float* Ap = A + (long)blockIdx.z * Kext;
    const float* Bp = B + (long)blockIdx.z * Kext;
    float* Cp = C + (long)blockIdx.z * csplit;

    // LDSM lane offsets (layouts validated in round 8).
    const int rowOffA = (lane & 7) + ((lane >> 3) & 1) * 8;
    const int colOffA = (lane >> 4) * 4;
    const int rowOffB = (lane & 7) + (lane >> 4) * 8;
    const int colOffB = ((lane >> 3) & 1) * 4;
    const uint32_t aLane = 4u * ((wm0 + rowOffA) * LDR + colOffA);
    const uint32_t bLane = 4u * ((wn0 + rowOffB) * LDR + colOffB);

    auto issue_tile = [&](int kt) {
        const uint32_t st = sbase + (uint32_t)(kt & 1) * SSZB;
        const int k0 = kt * BK;
#pragma unroll
        for (int i = 0; i < A_LD; i++) {
            int idx = tid + i * 256;
            int r = idx / (BK / 4), c = idx % (BK / 4);
            cp16(st + 4u * (r * LDR + c * 4), Ap + (brow + r) * lda + k0 + c * 4);
        }
#pragma unroll
        for (int i = 0; i < B_LD; i++) {
            int idx = tid + i * 256;
            int r = idx / (BK / 4), c = idx % (BK / 4);
            cp16(st + ASZB + 4u * (r * LDR + c * 4),
                 Bp + (bcol + r) * lda + k0 + c * 4);
        }
        cp_commit();
    };

    float acc[WM_ITER][WN_ITER][4];
#pragma unroll
    for (int i = 0; i < WM_ITER; i++)
#pragma unroll
        for (int j = 0; j < WN_ITER; j++)
#pragma unroll
            for (int t = 0; t < 4; t++) acc[i][j][t] = 0.0f;

    issue_tile(0);
    asm volatile("cp.async.wait_group 0;" ::: "memory");
    __syncthreads();

    for (int kt = 0; kt < NK; kt++) {
        if (kt + 1 < NK) issue_tile(kt + 1);

        const uint32_t st = sbase + (uint32_t)(kt & 1) * SSZB;
        const uint32_t aBase = st + aLane;
        const uint32_t bBase = st + ASZB + bLane;

#pragma unroll
        for (int ks = 0; ks < BK / 8; ks++) {
            uint32_t af[WM_ITER][4];
            uint32_t bq[WN_PAIRS][4];
#pragma unroll
            for (int i = 0; i < WM_ITER; i++) {
                ldsm_x4(af[i], aBase + 4u * (i * 16 * LDR) + ks * 32u);
                if (CVT_A) {
#pragma unroll
                    for (int t = 0; t < 4; t++) af[i][t] = as_tf32_bits(af[i][t]);
                }
            }
#pragma unroll
            for (int p = 0; p < WN_PAIRS; p++)
                ldsm_x4(bq[p], bBase + 4u * (p * 16 * LDR) + ks * 32u);
#pragma unroll
            for (int i = 0; i < WM_ITER; i++)
#pragma unroll
                for (int p = 0; p < WN_PAIRS; p++) {
                    mma_tf32(acc[i][2 * p], af[i], &bq[p][0]);
                    mma_tf32(acc[i][2 * p + 1], af[i], &bq[p][2]);
                }
        }

        if (kt + 1 < NK) asm volatile("cp.async.wait_group 0;" ::: "memory");
        __syncthreads();
    }

    // Epilogue: acc[i][j] -> rows (wm0+i*16+gid, +8), cols (wn0+j*8+2*tig, +1)
#pragma unroll
    for (int i = 0; i < WM_ITER; i++) {
#pragma unroll
        for (int j = 0; j < WN_ITER; j++) {
            long r = brow + wm0 + i * 16 + gid;
            long c = bcol + wn0 + j * 8 + tig * 2;
            float v0 = acc[i][j][0], v1 = acc[i][j][1];
            float v2 = acc[i][j][2], v3 = acc[i][j][3];
            if (ROUND_OUT) {
                v0 = round_tf32(v0);
                v1 = round_tf32(v1);
                v2 = round_tf32(v2);
                v3 = round_tf32(v3);
            }
            *reinterpret_cast<float2*>(Cp + r * N + c) = make_float2(v0, v1);
            *reinterpret_cast<float2*>(Cp + (r + 8) * N + c) = make_float2(v2, v3);
        }
    }
}

// RMSNorm over 4 split-K partials:
// g = (p0+p1+p2+p3 + bias) * rsqrt(mean(sq)+eps) * scale, rounded to tf32.
__global__ void rmsnorm4_kernel(const float* __restrict__ gin,
                                const float* __restrict__ bias,
                                const float* __restrict__ scale,
                                float* __restrict__ gout) {
    const int b = blockIdx.x;
    const int h = threadIdx.x;  // 256 threads
    const int idx = b * 256 + h;
    float v = gin[idx] + gin[262144 + idx];
    v += gin[2 * 262144 + idx];
    v += gin[3 * 262144 + idx];
    v += bias[h];
    float s = v * v;
#pragma unroll
    for (int o = 16; o > 0; o >>= 1) s += __shfl_xor_sync(0xFFFFFFFFu, s, o);
    __shared__ float ws[8];
    if ((h & 31) == 0) ws[h >> 5] = s;
    __syncthreads();
    float tot = 0.0f;
#pragma unroll
    for (int w = 0; w < 8; w++) tot += ws[w];
    float inv = rsqrtf(tot * (1.0f / 256.0f) + 1e-6f);
    gout[idx] = round_tf32(v * inv * scale[h]);
}

// One fused prep launch: round 4 weight tensors to tf32 (RNA), float4-wide.
// Block ranges: [0,32) tc | [32,544) gc | [544,1568) heads | [1568,2592) logit.
__global__ void round_all_weights_kernel(const float* __restrict__ s0, float* d0,
                                         const float* __restrict__ s1, float* d1,
                                         const float* __restrict__ s2, float* d2,
                                         const float* __restrict__ s3, float* d3) {
    const int blk = blockIdx.x;
    const float* src;
    float* dst;
    int idx;
    if (blk < 32) {
        src = s0; dst = d0; idx = blk * 256 + threadIdx.x;
    } else if (blk < 544) {
        src = s1; dst = d1; idx = (blk - 32) * 256 + threadIdx.x;
    } else if (blk < 1568) {
        src = s2; dst = d2; idx = (blk - 544) * 256 + threadIdx.x;
    } else {
        src = s3; dst = d3; idx = (blk - 1568) * 256 + threadIdx.x;
    }
    float4 v = reinterpret_cast<const float4*>(src)[idx];
    v.x = round_tf32(v.x);
    v.y = round_tf32(v.y);
    v.z = round_tf32(v.z);
    v.w = round_tf32(v.w);
    reinterpret_cast<float4*>(dst)[idx] = v;
}

extern "C" void kernel_launch(void* const* d_in, const int* in_sizes, int n_in,
                              void* d_out, int out_size) {
    const float* x         = (const float*)d_in[0];  // (1024, 64, 1024)
    const float* W_tc      = (const float*)d_in[1];  // (32, 1024)
    const float* W_gc      = (const float*)d_in[2];  // (256, 2048)
    const float* b_gc      = (const float*)d_in[3];  // (256,)
    const float* rms_scale = (const float*)d_in[4];  // (256,)
    const float* W_heads   = (const float*)d_in[5];  // (16, 256, 256)
    const float* W_logit   = (const float*)d_in[6];  // (4096, 256)
    float* out = (float*)d_out;                      // (1024, 16, 64, 64)

    float *flat, *graw4, *gg, *hr, *wtcR, *wgcR, *whR, *wlR;
    cudaGetSymbolAddress((void**)&flat, g_flat);
    cudaGetSymbolAddress((void**)&graw4, g_graw4);
    cudaGetSymbolAddress((void**)&gg, g_g);
    cudaGetSymbolAddress((void**)&hr, g_hr);
    cudaGetSymbolAddress((void**)&wtcR, g_WtcR);
    cudaGetSymbolAddress((void**)&wgcR, g_WgcR);
    cudaGetSymbolAddress((void**)&whR, g_WheadsR);
    cudaGetSymbolAddress((void**)&wlR, g_WlogitR);

    // Prep: one fused weight-rounding launch (2592 blocks).
    round_all_weights_kernel<<<2592, 256>>>(W_tc, wtcR, W_gc, wgcR, W_heads, whR,
                                            W_logit, wlR);

    // Stage A: M=65536, N=32, K=1024. BM=128, BN=32, BK=64, warps 8x1.
    // CVT on A frags (x raw), output rounded. smem 87,040 B -> 2 CTAs/SM.
    {
        auto k = gemm_ldsm<128, 32, 64, 8, 1, true, true>;
        size_t smem = 2 * (size_t)(128 + 32) * (64 + 4) * 4;
        cudaFuncSetAttribute(k, cudaFuncAttributeMaxDynamicSharedMemorySize, (int)smem);
        k<<<dim3(1, 512), 256, smem>>>(x, wtcR, flat, 32, 1024, 1024, 0);
    }
    // Stage B: split-K x4. M=1024, N=256, Kext=512 per chunk, lda=2048.
    // BM=64, BN=128, BK=32, warps 2x4. Partials -> graw4. smem 55,296 B.
    {
        auto k = gemm_ldsm<64, 128, 32, 2, 4, false, false>;
        size_t smem = 2 * (size_t)(64 + 128) * (32 + 4) * 4;
        cudaFuncSetAttribute(k, cudaFuncAttributeMaxDynamicSharedMemorySize, (int)smem);
        k<<<dim3(2, 16, 4), 256, smem>>>(flat, wgcR, graw4, 256, 512, 2048,
                                         (long)1024 * 256);
    }
    rmsnorm4_kernel<<<1024, 256>>>(graw4, b_gc, rms_scale, gg);

    // Stages C/D: BM=128, BN=256, BK=32, warps 2x4. smem 110,592 B -> 2 CTAs/SM.
    {
        size_t smem = 2 * (size_t)(128 + 256) * (32 + 4) * 4;
        auto kc = gemm_ldsm<128, 256, 32, 2, 4, false, true>;
        auto kd = gemm_ldsm<128, 256, 32, 2, 4, false, false>;
        cudaFuncSetAttribute(kc, cudaFuncAttributeMaxDynamicSharedMemorySize, (int)smem);
        cudaFuncSetAttribute(kd, cudaFuncAttributeMaxDynamicSharedMemorySize, (int)smem);
        // C: M=1024, N=4096, K=256 -> grid (16, 8).
        kc<<<dim3(16, 8), 256, smem>>>(gg, whR, hr, 4096, 256, 256, 0);
        // D: M=16384, N=4096, K=256 -> grid (16, 128).
        kd<<<dim3(16, 128), 256, smem>>>(hr, wlR, out, 4096, 256, 256, 0);
    }
}

// round 10
// speedup vs baseline: 2.1355x; 2.1355x over previous
#include <cuda_runtime.h>
#include <cstdint>

// ---------------------------------------------------------------------------
// Smolgen pipeline on GB300 (sm_103a), round 10:
//   prep: round all weights to tf32 (RNA), one fused launch
//   A: flat  = x @ W_tcR^T        (65536 x 32,  K=1024)  scalar-pipe (r8 cfg)
//   B: graw4 = flat @ W_gcR^T     split-K x4 partials    LDSM 64x128
//      rmsnorm: gg = norm(sum partials + bias), tf32-rounded
//   C: hr  = gg @ W_headsR^T      (1024 x 4096, K=256)   LDSM 128x128, occ 2
//   D: out = hr @ W_logitR^T      (16384 x 4096, K=256)  LDSM 128x128, occ 2
// C/D use 64-float accumulators so __launch_bounds__(256,2) fits WITHOUT
// register spills (r9's regression was 128-float acc + forced 128-reg cap).
// ---------------------------------------------------------------------------

__device__ float g_flat[1024 * 2048];
__device__ float g_graw4[4 * 1024 * 256];
__device__ float g_g[1024 * 256];
__device__ float g_hr[1024 * 4096];
__device__ float g_WtcR[32 * 1024];
__device__ float g_WgcR[256 * 2048];
__device__ float g_WheadsR[16 * 256 * 256];
__device__ float g_WlogitR[4096 * 256];

__device__ __forceinline__ float round_tf32(float x) {
    float y;
    asm("cvt.rna.tf32.f32 %0, %1;" : "=f"(y) : "f"(x));
    return y;
}
__device__ __forceinline__ uint32_t as_tf32(float x) {
    return __float_as_uint(round_tf32(x));
}

__device__ __forceinline__ void mma_tf32(float* d, const uint32_t* a, const uint32_t* b) {
    asm volatile(
        "mma.sync.aligned.m16n8k8.row.col.f32.tf32.tf32.f32 "
        "{%0,%1,%2,%3},{%4,%5,%6,%7},{%8,%9},{%0,%1,%2,%3};"
        : "+f"(d[0]), "+f"(d[1]), "+f"(d[2]), "+f"(d[3])
        : "r"(a[0]), "r"(a[1]), "r"(a[2]), "r"(a[3]), "r"(b[0]), "r"(b[1]));
}

__device__ __forceinline__ void ldsm_x4(uint32_t* r, uint32_t addr) {
    asm volatile(
        "ldmatrix.sync.aligned.m8n8.x4.shared.b16 {%0,%1,%2,%3}, [%4];"
        : "=r"(r[0]), "=r"(r[1]), "=r"(r[2]), "=r"(r[3])
        : "r"(addr));
}

__device__ __forceinline__ void cp16(uint32_t saddr, const float* gptr) {
    asm volatile("cp.async.cg.shared.global [%0], [%1], 16;" ::"r"(saddr), "l"(gptr));
}
__device__ __forceinline__ void cp_commit() { asm volatile("cp.async.commit_group;"); }
__device__ __forceinline__ uint32_t smem_u32(const void* p) {
    return (uint32_t)__cvta_generic_to_shared(p);
}

// =============== LDSM tf32 GEMM (stages B, C, D) — occupancy 2 ===============
// C[.,N] = A @ B^T over K-extent Kext, row stride lda for A and B.
// blockIdx.z = split-K chunk (A,B advance z*Kext floats; C advances z*csplit).
// Requires per-thread acc = BM*BN/256 <= 64 floats (no spills at 128-reg cap).
template <int BM, int BN, int BK, int WARPS_M, int WARPS_N, bool ROUND_OUT>
__global__ void __launch_bounds__(256, 2)
    gemm_ldsm(const float* __restrict__ A, const float* __restrict__ B,
              float* __restrict__ C, int N, int Kext, int lda, long csplit) {
    static_assert(WARPS_M * WARPS_N == 8, "8 warps");
    constexpr int WM_ITER = BM / (WARPS_M * 16);
    constexpr int WN_PAIRS = BN / (WARPS_N * 16);
    constexpr int WN_ITER = 2 * WN_PAIRS;
    static_assert(WM_ITER * WN_ITER * 4 <= 64, "acc must fit 128-reg cap");
    constexpr int LDR = BK + 4;
    constexpr int ASZB = BM * LDR * 4;
    constexpr int BSZB = BN * LDR * 4;
    constexpr int SSZB = ASZB + BSZB;
    constexpr int A_LD = BM * (BK / 4) / 256;
    constexpr int B_LD = BN * (BK / 4) / 256;
    static_assert(A_LD * 256 * 4 == BM * BK, "A chunks");
    static_assert(B_LD * 256 * 4 == BN * BK, "B chunks");

    extern __shared__ float smem[];
    const uint32_t sbase = smem_u32(smem);

    const int tid = threadIdx.x;
    const int warp = tid >> 5;
    const int lane = tid & 31;
    const int gid = lane >> 2;
    const int tig = lane & 3;
    const int wm0 = (warp / WARPS_N) * (WM_ITER * 16);
    const int wn0 = (warp % WARPS_N) * (WN_PAIRS * 16);
    const long brow = (long)blockIdx.y * BM;
    const long bcol = (long)blockIdx.x * BN;
    const int NK = Kext / BK;

    const float* Ap = A + (long)blockIdx.z * Kext;
    const float* Bp = B + (long)blockIdx.z * Kext;
    float* Cp = C + (long)blockIdx.z * csplit;

    // LDSM lane offsets (layout validated in round 8).
    const int rowOffA = (lane & 7) + ((lane >> 3) & 1) * 8;
    const int colOffA = (lane >> 4) * 4;
    const int rowOffB = (lane & 7) + (lane >> 4) * 8;
    const int colOffB = ((lane >> 3) & 1) * 4;
    const uint32_t aLane = 4u * ((wm0 + rowOffA) * LDR + colOffA);
    const uint32_t bLane = 4u * ((wn0 + rowOffB) * LDR + colOffB);

    auto issue_tile = [&](int kt) {
        const uint32_t st = sbase + (uint32_t)(kt & 1) * SSZB;
        const int k0 = kt * BK;
#pragma unroll
        for (int i = 0; i < A_LD; i++) {
            int idx = tid + i * 256;
            int r = idx / (BK / 4), c = idx % (BK / 4);
            cp16(st + 4u * (r * LDR + c * 4), Ap + (brow + r) * lda + k0 + c * 4);
        }
#pragma unroll
        for (int i = 0; i < B_LD; i++) {
            int idx = tid + i * 256;
            int r = idx / (BK / 4), c = idx % (BK / 4);
            cp16(st + ASZB + 4u * (r * LDR + c * 4),
                 Bp + (bcol + r) * lda + k0 + c * 4);
        }
        cp_commit();
    };

    float acc[WM_ITER][WN_ITER][4];
#pragma unroll
    for (int i = 0; i < WM_ITER; i++)
#pragma unroll
        for (int j = 0; j < WN_ITER; j++)
#pragma unroll
            for (int t = 0; t < 4; t++) acc[i][j][t] = 0.0f;

    issue_tile(0);
    asm volatile("cp.async.wait_group 0;" ::: "memory");
    __syncthreads();

    for (int kt = 0; kt < NK; kt++) {
        if (kt + 1 < NK) issue_tile(kt + 1);

        const uint32_t st = sbase + (uint32_t)(kt & 1) * SSZB;
        const uint32_t aBase = st + aLane;
        const uint32_t bBase = st + ASZB + bLane;

#pragma unroll
        for (int ks = 0; ks < BK / 8; ks++) {
            uint32_t af[WM_ITER][4];
            uint32_t bq[WN_PAIRS][4];
#pragma unroll
            for (int i = 0; i < WM_ITER; i++)
                ldsm_x4(af[i], aBase + 4u * (i * 16 * LDR) + ks * 32u);
#pragma unroll
            for (int p = 0; p < WN_PAIRS; p++)
                ldsm_x4(bq[p], bBase + 4u * (p * 16 * LDR) + ks * 32u);
#pragma unroll
            for (int i = 0; i < WM_ITER; i++)
#pragma unroll
                for (int p = 0; p < WN_PAIRS; p++) {
                    mma_tf32(acc[i][2 * p], af[i], &bq[p][0]);
                    mma_tf32(acc[i][2 * p + 1], af[i], &bq[p][2]);
                }
        }

        if (kt + 1 < NK) asm volatile("cp.async.wait_group 0;" ::: "memory");
        __syncthreads();
    }

#pragma unroll
    for (int i = 0; i < WM_ITER; i++) {
#pragma unroll
        for (int j = 0; j < WN_ITER; j++) {
            long r = brow + wm0 + i * 16 + gid;
            long c = bcol + wn0 + j * 8 + tig * 2;
            float v0 = acc[i][j][0], v1 = acc[i][j][1];
            float v2 = acc[i][j][2], v3 = acc[i][j][3];
            if (ROUND_OUT) {
                v0 = round_tf32(v0);
                v1 = round_tf32(v1);
                v2 = round_tf32(v2);
                v3 = round_tf32(v3);
            }
            *reinterpret_cast<float2*>(Cp + r * N + c) = make_float2(v0, v1);
            *reinterpret_cast<float2*>(Cp + (r + 8) * N + c) = make_float2(v2, v3);
        }
    }
}

// ================= scalar-LDS pipelined GEMM (stage A, r8 cfg) ===============
template <int BM, int BN, int BK, int WARPS_M, int WARPS_N, int WM_ITER, int WN_ITER,
          int STAGES, bool CVT_A, bool ROUND_OUT>
__global__ void __launch_bounds__(WARPS_M* WARPS_N * 32, 1)
    gemm_tf32_pipe(const float* __restrict__ A, const float* __restrict__ B,
                   float* __restrict__ C, int M, int N, int K) {
    constexpr int THREADS = WARPS_M * WARPS_N * 32;
    constexpr int PAD = 4;
    constexpr int LDR = BK + PAD;
    constexpr int ASZ = BM * LDR;
    constexpr int BSZ = BN * LDR;
    constexpr int SSZ = ASZ + BSZ;

    extern __shared__ float smem[];

    const int tid = threadIdx.x;
    const int warp = tid >> 5;
    const int lane = tid & 31;
    const int gid = lane >> 2;
    const int tig = lane & 3;
    const int warp_m = warp / WARPS_N;
    const int warp_n = warp % WARPS_N;
    const int wm0 = warp_m * (WM_ITER * 16);
    const int wn0 = warp_n * (WN_ITER * 8);
    const long brow = (long)blockIdx.y * BM;
    const long bcol = (long)blockIdx.x * BN;

    constexpr int A_LD = (BM * BK / 4) / THREADS;
    constexpr int B_LD = (BN * BK / 4) / THREADS;
    const int NK = K / BK;

    auto issue_tile = [&](int kt) {
        const int st = kt % STAGES;
        float* As = smem + st * SSZ;
        float* Bs = As + ASZ;
        const int k0 = kt * BK;
#pragma unroll
        for (int i = 0; i < A_LD; i++) {
            int idx = tid + i * THREADS;
            int r = idx / (BK / 4);
            int c4 = (idx % (BK / 4)) * 4;
            cp16(smem_u32(&As[r * LDR + c4]), A + (brow + r) * K + k0 + c4);
        }
#pragma unroll
        for (int i = 0; i < B_LD; i++) {
            int idx = tid + i * THREADS;
            int r = idx / (BK / 4);
            int c4 = (idx % (BK / 4)) * 4;
            cp16(smem_u32(&Bs[r * LDR + c4]), B + (bcol + r) * K + k0 + c4);
        }
        cp_commit();
    };

    float acc[WM_ITER][WN_ITER][4];
#pragma unroll
    for (int i = 0; i < WM_ITER; i++)
#pragma unroll
        for (int j = 0; j < WN_ITER; j++)
#pragma unroll
            for (int t = 0; t < 4; t++) acc[i][j][t] = 0.0f;

    issue_tile(0);
    if (NK > 1) issue_tile(1);

    for (int kt = 0; kt < NK; kt++) {
        if (kt + 1 < NK)
            asm volatile("cp.async.wait_group 1;" ::: "memory");
        else
            asm volatile("cp.async.wait_group 0;" ::: "memory");
        __syncthreads();
        if (kt + 2 < NK) issue_tile(kt + 2);

        const int st = kt % STAGES;
        const float* As = smem + st * SSZ;
        const float* Bs = As + ASZ;

#pragma unroll
        for (int ks = 0; ks < BK / 8; ks++) {
            uint32_t af[WM_ITER][4];
            uint32_t bf[WN_ITER][2];
#pragma unroll
            for (int i = 0; i < WM_ITER; i++) {
                int r = wm0 + i * 16;
                if (CVT_A) {
                    af[i][0] = as_tf32(As[(r + gid) * LDR + ks * 8 + tig]);
                    af[i][1] = as_tf32(As[(r + gid + 8) * LDR + ks * 8 + tig]);
                    af[i][2] = as_tf32(As[(r + gid) * LDR + ks * 8 + tig + 4]);
                    af[i][3] = as_tf32(As[(r + gid + 8) * LDR + ks * 8 + tig + 4]);
                } else {
                    af[i][0] = __float_as_uint(As[(r + gid) * LDR + ks * 8 + tig]);
                    af[i][1] = __float_as_uint(As[(r + gid + 8) * LDR + ks * 8 + tig]);
                    af[i][2] = __float_as_uint(As[(r + gid) * LDR + ks * 8 + tig + 4]);
                    af[i][3] = __float_as_uint(As[(r + gid + 8) * LDR + ks * 8 + tig + 4]);
                }
            }
#pragma unroll
            for (int j = 0; j < WN_ITER; j++) {
                int c = wn0 + j * 8;
                bf[j][0] = __float_as_uint(Bs[(c + gid) * LDR + ks * 8 + tig]);
                bf[j][1] = __float_as_uint(Bs[(c + gid) * LDR + ks * 8 + tig + 4]);
            }
#pragma unroll
            for (int i = 0; i < WM_ITER; i++)
#pragma unroll
                for (int j = 0; j < WN_ITER; j++) mma_tf32(acc[i][j], af[i], bf[j]);
        }
    }

#pragma unroll
    for (int i = 0; i < WM_ITER; i++) {
#pragma unroll
        for (int j = 0; j < WN_ITER; j++) {
            long r = brow + wm0 + i * 16 + gid;
            long c = bcol + wn0 + j * 8 + tig * 2;
            float v0 = acc[i][j][0], v1 = acc[i][j][1];
            float v2 = acc[i][j][2], v3 = acc[i][j][3];
            if (ROUND_OUT) {
                v0 = round_tf32(v0);
                v1 = round_tf32(v1);
                v2 = round_tf32(v2);
                v3 = round_tf32(v3);
            }
            *reinterpret_cast<float2*>(C + r * N + c) = make_float2(v0, v1);
            *reinterpret_cast<float2*>(C + (r + 8) * N + c) = make_float2(v2, v3);
        }
    }
}

// RMSNorm over 4 split-K partials, tf32-rounded output.
__global__ void rmsnorm4_kernel(const float* __restrict__ gin,
                                const float* __restrict__ bias,
                                const float* __restrict__ scale,
                                float* __restrict__ gout) {
    const int b = blockIdx.x;
    const int h = threadIdx.x;  // 256 threads
    const int idx = b * 256 + h;
    float v = gin[idx] + gin[262144 + idx];
    v += gin[2 * 262144 + idx];
    v += gin[3 * 262144 + idx];
    v += bias[h];
    float s = v * v;
#pragma unroll
    for (int o = 16; o > 0; o >>= 1) s += __shfl_xor_sync(0xFFFFFFFFu, s, o);
    __shared__ float ws[8];
    if ((h & 31) == 0) ws[h >> 5] = s;
    __syncthreads();
    float tot = 0.0f;
#pragma unroll
    for (int w = 0; w < 8; w++) tot += ws[w];
    float inv = rsqrtf(tot * (1.0f / 256.0f) + 1e-6f);
    gout[idx] = round_tf32(v * inv * scale[h]);
}

// One fused prep launch: round 4 weight tensors to tf32 (RNA), float4-wide.
__global__ void round_all_weights_kernel(const float* __restrict__ s0, float* d0,
                                         const float* __restrict__ s1, float* d1,
                                         const float* __restrict__ s2, float* d2,
                                         const float* __restrict__ s3, float* d3) {
    const int blk = blockIdx.x;
    const float* src;
    float* dst;
    int idx;
    if (blk < 32) {
        src = s0; dst = d0; idx = blk * 256 + threadIdx.x;
    } else if (blk < 544) {
        src = s1; dst = d1; idx = (blk - 32) * 256 + threadIdx.x;
    } else if (blk < 1568) {
        src = s2; dst = d2; idx = (blk - 544) * 256 + threadIdx.x;
    } else {
        src = s3; dst = d3; idx = (blk - 1568) * 256 + threadIdx.x;
    }
    float4 v = reinterpret_cast<const float4*>(src)[idx];
    v.x = round_tf32(v.x);
    v.y = round_tf32(v.y);
    v.z = round_tf32(v.z);
    v.w = round_tf32(v.w);
    reinterpret_cast<float4*>(dst)[idx] = v;
}

extern "C" void kernel_launch(void* const* d_in, const int* in_sizes, int n_in,
                              void* d_out, int out_size) {
    const float* x         = (const float*)d_in[0];  // (1024, 64, 1024)
    const float* W_tc      = (const float*)d_in[1];  // (32, 1024)
    const float* W_gc      = (const float*)d_in[2];  // (256, 2048)
    const float* b_gc      = (const float*)d_in[3];  // (256,)
    const float* rms_scale = (const float*)d_in[4];  // (256,)
    const float* W_heads   = (const float*)d_in[5];  // (16, 256, 256)
    const float* W_logit   = (const float*)d_in[6];  // (4096, 256)
    float* out = (float*)d_out;                      // (1024, 16, 64, 64)

    float *flat, *graw4, *gg, *hr, *wtcR, *wgcR, *whR, *wlR;
    cudaGetSymbolAddress((void**)&flat, g_flat);
    cudaGetSymbolAddress((void**)&graw4, g_graw4);
    cudaGetSymbolAddress((void**)&gg, g_g);
    cudaGetSymbolAddress((void**)&hr, g_hr);
    cudaGetSymbolAddress((void**)&wtcR, g_WtcR);
    cudaGetSymbolAddress((void**)&wgcR, g_WgcR);
    cudaGetSymbolAddress((void**)&whR, g_WheadsR);
    cudaGetSymbolAddress((void**)&wlR, g_WlogitR);

    // Prep: one fused weight-rounding launch (2592 blocks).
    round_all_weights_kernel<<<2592, 256>>>(W_tc, wtcR, W_gc, wgcR, W_heads, whR,
                                            W_logit, wlR);

    constexpr int PAD = 4;
    // Stage A: r8 config. M=65536, N=32, K=1024; CVT on A frags, round output.
    {
        auto k = gemm_tf32_pipe<128, 32, 32, 8, 1, 1, 4, 3, true, true>;
        size_t smem = 3 * (size_t)(128 + 32) * (32 + PAD) * sizeof(float);
        cudaFuncSetAttribute(k, cudaFuncAttributeMaxDynamicSharedMemorySize, (int)smem);
        k<<<dim3(1, 512), 256, smem>>>(x, wtcR, flat, 65536, 32, 1024);
    }
    // Stage B: split-K x4 LDSM. Kext=512/chunk, lda=2048. acc=32 fl -> no spill.
    {
        auto k = gemm_ldsm<64, 128, 32, 2, 4, false>;
        size_t smem = 2 * (size_t)(64 + 128) * (32 + 4) * 4;
        cudaFuncSetAttribute(k, cudaFuncAttributeMaxDynamicSharedMemorySize, (int)smem);
        k<<<dim3(2, 16, 4), 256, smem>>>(flat, wgcR, graw4, 256, 512, 2048,
                                         (long)1024 * 256);
    }
    rmsnorm4_kernel<<<1024, 256>>>(graw4, b_gc, rms_scale, gg);

    // Stages C/D: 128x128 CTA tiles, acc=64 fl, 2 CTAs/SM, smem 73,728 B.
    {
        size_t smem = 2 * (size_t)(128 + 128) * (32 + 4) * 4;
        auto kc = gemm_ldsm<128, 128, 32, 2, 4, true>;
        auto kd = gemm_ldsm<128, 128, 32, 2, 4, false>;
        cudaFuncSetAttribute(kc, cudaFuncAttributeMaxDynamicSharedMemorySize, (int)smem);
        cudaFuncSetAttribute(kd, cudaFuncAttributeMaxDynamicSharedMemorySize, (int)smem);
        // C: M=1024, N=4096 -> grid (32, 8).
        kc<<<dim3(32, 8), 256, smem>>>(gg, whR, hr, 4096, 256, 256, 0);
        // D: M=16384, N=4096 -> grid (32, 128).
        kd<<<dim3(32, 128), 256, smem>>>(hr, wlR, out, 4096, 256, 256, 0);
    }
}

// round 12
// speedup vs baseline: 2.8610x; 1.3397x over previous
#include <cuda_runtime.h>
#include <cuda_fp16.h>
#include <cstdint>

// ---------------------------------------------------------------------------
// Smolgen pipeline on GB300 (sm_103a), round 12 (= round 11 minus compile bug):
// fp16-input / fp32-accum mma.sync for stages B/C/D (fp16 significand ==
// tf32 significand, so numerics match the tf32 pipeline), tf32 scalar-pipe
// for stage A.
//   prep: W_tc->tf32, {W_gc,W_heads,W_logit}->fp16, one fused launch
//   A: flatH = x @ W_tcR^T        (65536 x 32,  K=1024)  tf32, fp16 output
//   B: graw4 = flatH @ WgcH^T     split-K x4 fp32 partials  fp16 LDSM
//      rmsnorm4: ggH = norm(sum + bias) as fp16
//   C: hrH = ggH @ WheadsH^T      (1024 x 4096, K=256)   fp16 LDSM
//   D: out = hrH @ WlogitH^T      (16384 x 4096, K=256)  fp16 LDSM, fp32 out
// ---------------------------------------------------------------------------

__device__ __half g_flatH[1024 * 2048];
__device__ float g_graw4[4 * 1024 * 256];
__device__ __half g_gH[1024 * 256];
__device__ __half g_hrH[1024 * 4096];
__device__ float g_WtcR[32 * 1024];
__device__ __half g_WgcH[256 * 2048];
__device__ __half g_WheadsH[16 * 256 * 256];
__device__ __half g_WlogitH[4096 * 256];

__device__ __forceinline__ float round_tf32(float x) {
    float y;
    asm("cvt.rna.tf32.f32 %0, %1;" : "=f"(y) : "f"(x));
    return y;
}
__device__ __forceinline__ uint32_t as_tf32(float x) {
    return __float_as_uint(round_tf32(x));
}

__device__ __forceinline__ void mma_tf32(float* d, const uint32_t* a, const uint32_t* b) {
    asm volatile(
        "mma.sync.aligned.m16n8k8.row.col.f32.tf32.tf32.f32 "
        "{%0,%1,%2,%3},{%4,%5,%6,%7},{%8,%9},{%0,%1,%2,%3};"
        : "+f"(d[0]), "+f"(d[1]), "+f"(d[2]), "+f"(d[3])
        : "r"(a[0]), "r"(a[1]), "r"(a[2]), "r"(a[3]), "r"(b[0]), "r"(b[1]));
}
__device__ __forceinline__ void mma_f16(float* d, const uint32_t* a, uint32_t b0,
                                        uint32_t b1) {
    asm volatile(
        "mma.sync.aligned.m16n8k16.row.col.f32.f16.f16.f32 "
        "{%0,%1,%2,%3},{%4,%5,%6,%7},{%8,%9},{%0,%1,%2,%3};"
        : "+f"(d[0]), "+f"(d[1]), "+f"(d[2]), "+f"(d[3])
        : "r"(a[0]), "r"(a[1]), "r"(a[2]), "r"(a[3]), "r"(b0), "r"(b1));
}

__device__ __forceinline__ void ldsm_x4(uint32_t* r, uint32_t addr) {
    asm volatile(
        "ldmatrix.sync.aligned.m8n8.x4.shared.b16 {%0,%1,%2,%3}, [%4];"
        : "=r"(r[0]), "=r"(r[1]), "=r"(r[2]), "=r"(r[3])
        : "r"(addr));
}

__device__ __forceinline__ void cp16(uint32_t saddr, const void* gptr) {
    asm volatile("cp.async.cg.shared.global [%0], [%1], 16;" ::"r"(saddr), "l"(gptr));
}
__device__ __forceinline__ void cp_commit() { asm volatile("cp.async.commit_group;"); }
__device__ __forceinline__ uint32_t smem_u32(const void* p) {
    return (uint32_t)__cvta_generic_to_shared(p);
}

// ================ fp16 LDSM GEMM (stages B, C, D) — occupancy 2 =============
// C[.,N] = A @ B^T over K-extent Kext (halves), row stride lda (halves).
// blockIdx.z = split-K chunk (A,B advance z*Kext halves; C advances z*csplit).
// A,B fp16; accumulate fp32. OUT_HALF: write __half, else fp32.
// BK in halves (64 => 128-byte rows). acc = BM*BN/256 <= 64 floats.
template <int BM, int BN, int BK, int WARPS_M, int WARPS_N, bool OUT_HALF>
__global__ void __launch_bounds__(256, 2)
    gemm_h16(const __half* __restrict__ A, const __half* __restrict__ B, void* Cv,
             int N, int Kext, int lda, long csplit) {
    static_assert(WARPS_M * WARPS_N == 8, "8 warps");
    constexpr int WM_ITER = BM / (WARPS_M * 16);
    constexpr int WN_PAIRS = BN / (WARPS_N * 16);
    static_assert(WM_ITER * WN_PAIRS * 2 * 4 <= 64, "acc fits 128-reg cap");
    constexpr int LDR = BK + 8;              // halves; 144B rows: conflict-free
    constexpr int ASZB = BM * LDR * 2;       // bytes
    constexpr int BSZB = BN * LDR * 2;
    constexpr int SSZB = ASZB + BSZB;
    constexpr int A_LD = BM * (BK / 8) / 256;
    constexpr int B_LD = BN * (BK / 8) / 256;
    static_assert(A_LD * 256 * 8 == BM * BK, "A chunks");
    static_assert(B_LD * 256 * 8 == BN * BK, "B chunks");

    extern __shared__ char smemc[];
    const uint32_t sbase = smem_u32(smemc);

    const int tid = threadIdx.x;
    const int warp = tid >> 5;
    const int lane = tid & 31;
    const int gid = lane >> 2;
    const int tig = lane & 3;
    const int wm0 = (warp / WARPS_N) * (WM_ITER * 16);
    const int wn0 = (warp % WARPS_N) * (WN_PAIRS * 16);
    const long brow = (long)blockIdx.y * BM;
    const long bcol = (long)blockIdx.x * BN;
    const int NK = Kext / BK;

    const __half* Ap = A + (long)blockIdx.z * Kext;
    const __half* Bp = B + (long)blockIdx.z * Kext;

    // ldmatrix lane offsets: lanes 0-15 -> rows 0-15 (k lo 8), 16-31 -> k hi 8.
    const int rowOff = lane & 15;
    const int colOff = (lane >> 4) * 8;
    const uint32_t aLane = 2u * ((wm0 + rowOff) * LDR + colOff);
    const uint32_t bLane = 2u * ((wn0 + rowOff) * LDR + colOff);

    auto issue_tile = [&](int kt) {
        const uint32_t st = sbase + (uint32_t)(kt & 1) * SSZB;
        const int k0 = kt * BK;
#pragma unroll
        for (int i = 0; i < A_LD; i++) {
            int idx = tid + i * 256;
            int r = idx / (BK / 8), c = idx % (BK / 8);
            cp16(st + 2u * (r * LDR) + c * 16u, Ap + (brow + r) * lda + k0 + c * 8);
        }
#pragma unroll
        for (int i = 0; i < B_LD; i++) {
            int idx = tid + i * 256;
            int r = idx / (BK / 8), c = idx % (BK / 8);
            cp16(st + ASZB + 2u * (r * LDR) + c * 16u,
                 Bp + (bcol + r) * lda + k0 + c * 8);
        }
        cp_commit();
    };

    float acc[WM_ITER][2 * WN_PAIRS][4];
#pragma unroll
    for (int i = 0; i < WM_ITER; i++)
#pragma unroll
        for (int j = 0; j < 2 * WN_PAIRS; j++)
#pragma unroll
            for (int t = 0; t < 4; t++) acc[i][j][t] = 0.0f;

    issue_tile(0);
    asm volatile("cp.async.wait_group 0;" ::: "memory");
    __syncthreads();

    for (int kt = 0; kt < NK; kt++) {
        if (kt + 1 < NK) issue_tile(kt + 1);

        const uint32_t st = sbase + (uint32_t)(kt & 1) * SSZB;
        const uint32_t aBase = st + aLane;
        const uint32_t bBase = st + ASZB + bLane;

#pragma unroll
        for (int ks = 0; ks < BK / 16; ks++) {
            uint32_t af[WM_ITER][4];
            uint32_t bq[WN_PAIRS][4];
#pragma unroll
            for (int i = 0; i < WM_ITER; i++)
                ldsm_x4(af[i], aBase + 2u * (i * 16 * LDR) + ks * 32u);
#pragma unroll
            for (int p = 0; p < WN_PAIRS; p++)
                ldsm_x4(bq[p], bBase + 2u * (p * 16 * LDR) + ks * 32u);
#pragma unroll
            for (int i = 0; i < WM_ITER; i++)
#pragma unroll
                for (int p = 0; p < WN_PAIRS; p++) {
                    // n-tile 2p: B rows wn0+p*16+0..7 -> regs {0,2}
                    mma_f16(acc[i][2 * p], af[i], bq[p][0], bq[p][2]);
                    // n-tile 2p+1: B rows wn0+p*16+8..15 -> regs {1,3}
                    mma_f16(acc[i][2 * p + 1], af[i], bq[p][1], bq[p][3]);
                }
        }

        if (kt + 1 < NK) asm volatile("cp.async.wait_group 0;" ::: "memory");
        __syncthreads();
    }

    // Epilogue: acc[i][2p+h] -> rows (wm0+i*16+gid, +8),
    //           cols bcol+wn0+p*16+h*8+tig*2 (+1).
#pragma unroll
    for (int i = 0; i < WM_ITER; i++) {
#pragma unroll
        for (int p = 0; p < WN_PAIRS; p++) {
#pragma unroll
            for (int h = 0; h < 2; h++) {
                const float* a4 = acc[i][2 * p + h];
                long r = brow + wm0 + i * 16 + gid;
                long c = bcol + wn0 + p * 16 + h * 8 + tig * 2;
                if (OUT_HALF) {
                    __half* Ch = (__half*)Cv;
                    *reinterpret_cast<__half2*>(Ch + r * N + c) =
                        __floats2half2_rn(a4[0], a4[1]);
                    *reinterpret_cast<__half2*>(Ch + (r + 8) * N + c) =
                        __floats2half2_rn(a4[2], a4[3]);
                } else {
                    float* Cf = (float*)Cv + (long)blockIdx.z * csplit;
                    *reinterpret_cast<float2*>(Cf + r * N + c) =
                        make_float2(a4[0], a4[1]);
                    *reinterpret_cast<float2*>(Cf + (r + 8) * N + c) =
                        make_float2(a4[2], a4[3]);
                }
            }
        }
    }
}

// ============== scalar-LDS tf32 pipelined GEMM (stage A, r8 cfg) =============
// Output written as fp16 (__half) for the fp16 downstream stages.
template <int BM, int BN, int BK, int WARPS_M, int WARPS_N, int WM_ITER, int WN_ITER,
          int STAGES>
__global__ void __launch_bounds__(WARPS_M* WARPS_N * 32, 1)
    gemm_tf32_outh(const float* __restrict__ A, const float* __restrict__ B,
                   __half* __restrict__ C, int M, int N, int K) {
    constexpr int THREADS = WARPS_M * WARPS_N * 32;
    constexpr int PAD = 4;
    constexpr int LDR = BK + PAD;
    constexpr int ASZ = BM * LDR;
    constexpr int BSZ = BN * LDR;
    constexpr int SSZ = ASZ + BSZ;

    extern __shared__ float smem[];

    const int tid = threadIdx.x;
    const int warp = tid >> 5;
    const int lane = tid & 31;
    const int gid = lane >> 2;
    const int tig = lane & 3;
    const int warp_m = warp / WARPS_N;
    const int warp_n = warp % WARPS_N;
    const int wm0 = warp_m * (WM_ITER * 16);
    const int wn0 = warp_n * (WN_ITER * 8);
    const long brow = (long)blockIdx.y * BM;
    const long bcol = (long)blockIdx.x * BN;

    constexpr int A_LD = (BM * BK / 4) / THREADS;
    constexpr int B_LD = (BN * BK / 4) / THREADS;
    const int NK = K / BK;

    auto issue_tile = [&](int kt) {
        const int st = kt % STAGES;
        float* As = smem + st * SSZ;
        float* Bs = As + ASZ;
        const int k0 = kt * BK;
#pragma unroll
        for (int i = 0; i < A_LD; i++) {
            int idx = tid + i * THREADS;
            int r = idx / (BK / 4);
            int c4 = (idx % (BK / 4)) * 4;
            cp16(smem_u32(&As[r * LDR + c4]), A + (brow + r) * K + k0 + c4);
        }
#pragma unroll
        for (int i = 0; i < B_LD; i++) {
            int idx = tid + i * THREADS;
            int r = idx / (BK / 4);
            int c4 = (idx % (BK / 4)) * 4;
            cp16(smem_u32(&Bs[r * LDR + c4]), B + (bcol + r) * K + k0 + c4);
        }
        cp_commit();
    };

    float acc[WM_ITER][WN_ITER][4];
#pragma unroll
    for (int i = 0; i < WM_ITER; i++)
#pragma unroll
        for (int j = 0; j < WN_ITER; j++)
#pragma unroll
            for (int t = 0; t < 4; t++) acc[i][j][t] = 0.0f;

    issue_tile(0);
    if (NK > 1) issue_tile(1);

    for (int kt = 0; kt < NK; kt++) {
        if (kt + 1 < NK)
            asm volatile("cp.async.wait_group 1;" ::: "memory");
        else
            asm volatile("cp.async.wait_group 0;" ::: "memory");
        __syncthreads();
        if (kt + 2 < NK) issue_tile(kt + 2);

        const int st = kt % STAGES;
        const float* As = smem + st * SSZ;
        const float* Bs = As + ASZ;

#pragma unroll
        for (int ks = 0; ks < BK / 8; ks++) {
            uint32_t af[WM_ITER][4];
            uint32_t bf[WN_ITER][2];
#pragma unroll
            for (int i = 0; i < WM_ITER; i++) {
                int r = wm0 + i * 16;
                af[i][0] = as_tf32(As[(r + gid) * LDR + ks * 8 + tig]);
                af[i][1] = as_tf32(As[(r + gid + 8) * LDR + ks * 8 + tig]);
                af[i][2] = as_tf32(As[(r + gid) * LDR + ks * 8 + tig + 4]);
                af[i][3] = as_tf32(As[(r + gid + 8) * LDR + ks * 8 + tig + 4]);
            }
#pragma unroll
            for (int j = 0; j < WN_ITER; j++) {
                int c = wn0 + j * 8;
                bf[j][0] = __float_as_uint(Bs[(c + gid) * LDR + ks * 8 + tig]);
                bf[j][1] = __float_as_uint(Bs[(c + gid) * LDR + ks * 8 + tig + 4]);
            }
#pragma unroll
            for (int i = 0; i < WM_ITER; i++)
#pragma unroll
                for (int j = 0; j < WN_ITER; j++) mma_tf32(acc[i][j], af[i], bf[j]);
        }
    }

#pragma unroll
    for (int i = 0; i < WM_ITER; i++) {
#pragma unroll
        for (int j = 0; j < WN_ITER; j++) {
            long r = brow + wm0 + i * 16 + gid;
            long c = bcol + wn0 + j * 8 + tig * 2;
            *reinterpret_cast<__half2*>(C + r * N + c) =
                __floats2half2_rn(acc[i][j][0], acc[i][j][1]);
            *reinterpret_cast<__half2*>(C + (r + 8) * N + c) =
                __floats2half2_rn(acc[i][j][2], acc[i][j][3]);
        }
    }
}

// RMSNorm over 4 split-K partials; fp16 output.
__global__ void rmsnorm4_kernel(const float* __restrict__ gin,
                                const float* __restrict__ bias,
                                const float* __restrict__ scale,
                                __half* __restrict__ gout) {
    const int b = blockIdx.x;
    const int h = threadIdx.x;  // 256 threads
    const int idx = b * 256 + h;
    float v = gin[idx] + gin[262144 + idx];
    v += gin[2 * 262144 + idx];
    v += gin[3 * 262144 + idx];
    v += bias[h];
    float s = v * v;
#pragma unroll
    for (int o = 16; o > 0; o >>= 1) s += __shfl_xor_sync(0xFFFFFFFFu, s, o);
    __shared__ float ws[8];
    if ((h & 31) == 0) ws[h >> 5] = s;
    __syncthreads();
    float tot = 0.0f;
#pragma unroll
    for (int w = 0; w < 8; w++) tot += ws[w];
    float inv = rsqrtf(tot * (1.0f / 256.0f) + 1e-6f);
    gout[idx] = __float2half_rn(v * inv * scale[h]);
}

// Fused prep: W_tc -> tf32 fp32; W_gc/W_heads/W_logit -> fp16. float4-wide.
// Blocks: [0,32) tc | [32,544) gc | [544,1568) heads | [1568,2592) logit.
__global__ void prep_weights_kernel(const float* __restrict__ s0, float* d0,
                                    const float* __restrict__ s1, __half* d1,
                                    const float* __restrict__ s2, __half* d2,
                                    const float* __restrict__ s3, __half* d3) {
    const int blk = blockIdx.x;
    if (blk < 32) {
        int idx = blk * 256 + threadIdx.x;
        float4 v = reinterpret_cast<const float4*>(s0)[idx];
        v.x = round_tf32(v.x);
        v.y = round_tf32(v.y);
        v.z = round_tf32(v.z);
        v.w = round_tf32(v.w);
        reinterpret_cast<float4*>(d0)[idx] = v;
        return;
    }
    const float* src;
    __half* dst;
    int idx;
    if (blk < 544) {
        src = s1; dst = d1; idx = (blk - 32) * 256 + threadIdx.x;
    } else if (blk < 1568) {
        src = s2; dst = d2; idx = (blk - 544) * 256 + threadIdx.x;
    } else {
        src = s3; dst = d3; idx = (blk - 1568) * 256 + threadIdx.x;
    }
    float4 v = reinterpret_cast<const float4*>(src)[idx];
    reinterpret_cast<__half2*>(dst)[idx * 2 + 0] = __floats2half2_rn(v.x, v.y);
    reinterpret_cast<__half2*>(dst)[idx * 2 + 1] = __floats2half2_rn(v.z, v.w);
}

extern "C" void kernel_launch(void* const* d_in, const int* in_sizes, int n_in,
                              void* d_out, int out_size) {
    const float* x         = (const float*)d_in[0];  // (1024, 64, 1024)
    const float* W_tc      = (const float*)d_in[1];  // (32, 1024)
    const float* W_gc      = (const float*)d_in[2];  // (256, 2048)
    const float* b_gc      = (const float*)d_in[3];  // (256,)
    const float* rms_scale = (const float*)d_in[4];  // (256,)
    const float* W_heads   = (const float*)d_in[5];  // (16, 256, 256)
    const float* W_logit   = (const float*)d_in[6];  // (4096, 256)
    float* out = (float*)d_out;                      // (1024, 16, 64, 64)

    __half *flatH, *ggH, *hrH, *wgcH, *whH, *wlH;
    float *graw4, *wtcR;
    cudaGetSymbolAddress((void**)&flatH, g_flatH);
    cudaGetSymbolAddress((void**)&graw4, g_graw4);
    cudaGetSymbolAddress((void**)&ggH, g_gH);
    cudaGetSymbolAddress((void**)&hrH, g_hrH);
    cudaGetSymbolAddress((void**)&wtcR, g_WtcR);
    cudaGetSymbolAddress((void**)&wgcH, g_WgcH);
    cudaGetSymbolAddress((void**)&whH, g_WheadsH);
    cudaGetSymbolAddress((void**)&wlH, g_WlogitH);

    // Prep (2592 blocks).
    prep_weights_kernel<<<2592, 256>>>(W_tc, wtcR, W_gc, wgcH, W_heads, whH,
                                       W_logit, wlH);

    constexpr int PAD = 4;
    // Stage A: tf32 scalar pipe (r8 cfg), fp16 output.
    {
        auto k = gemm_tf32_outh<128, 32, 32, 8, 1, 1, 4, 3>;
        size_t smem = 3 * (size_t)(128 + 32) * (32 + PAD) * sizeof(float);
        cudaFuncSetAttribute(k, cudaFuncAttributeMaxDynamicSharedMemorySize, (int)smem);
        k<<<dim3(1, 512), 256, smem>>>(x, wtcR, flatH, 65536, 32, 1024);
    }
    // Stage B: fp16, split-K x4. BM=64,BN=128,BK=64h; Kext=512h, lda=2048h.
    {
        auto k = gemm_h16<64, 128, 64, 2, 4, false>;
        size_t smem = 2 * (size_t)(64 + 128) * (64 + 8) * 2;  // 55,296 B
        cudaFuncSetAttribute(k, cudaFuncAttributeMaxDynamicSharedMemorySize, (int)smem);
        k<<<dim3(2, 16, 4), 256, smem>>>(flatH, wgcH, graw4, 256, 512, 2048,
                                         (long)1024 * 256);
    }
    rmsnorm4_kernel<<<1024, 256>>>(graw4, b_gc, rms_scale, ggH);

    // Stages C/D: fp16, BM=128,BN=128,BK=64h, occ 2, smem 73,728 B.
    {
        size_t smem = 2 * (size_t)(128 + 128) * (64 + 8) * 2;
        auto kc = gemm_h16<128, 128, 64, 2, 4, true>;
        auto kd = gemm_h16<128, 128, 64, 2, 4, false>;
        cudaFuncSetAttribute(kc, cudaFuncAttributeMaxDynamicSharedMemorySize, (int)smem);
        cudaFuncSetAttribute(kd, cudaFuncAttributeMaxDynamicSharedMemorySize, (int)smem);
        // C: M=1024, N=4096, K=256 -> grid (32, 8).
        kc<<<dim3(32, 8), 256, smem>>>(ggH, whH, hrH, 4096, 256, 256, 0);
        // D: M=16384, N=4096, K=256 -> grid (32, 128).
        kd<<<dim3(32, 128), 256, smem>>>(hrH, wlH, out, 4096, 256, 256, 0);
    }
}

// round 13
// speedup vs baseline: 3.2310x; 1.1293x over previous
#include <cuda_runtime.h>
#include <cuda_fp16.h>
#include <cstdint>

// ---------------------------------------------------------------------------
// Smolgen pipeline on GB300 (sm_103a), round 13:
//   prep: W_tc->tf32, {W_gc,W_heads,W_logit}->fp16, one fused launch
//   A: flatH = x @ W_tcR^T        (65536 x 32,  K=1024)  tf32 LDSM, fp16 out
//   B: graw4 = flatH @ WgcH^T     split-K x4 fp32 partials  fp16 LDSM, 3-stage
//      rmsnorm4: ggH = norm(sum + bias) as fp16
//   C: hrH = ggH @ WheadsH^T      (1024 x 4096, K=256)   fp16 LDSM, 3-stage
//   D: out = hrH @ WlogitH^T      (16384 x 4096, K=256)  fp16 LDSM, 3-stage
// Changes vs r12: 3-stage cp.async rings for B/C/D (deeper prefetch, smem
// 110.6KB keeps occ 2 on C/D); stage A switched to ldmatrix fragments with
// post-LDSM tf32 CVT (issue-lean; r9-validated layout), occ 2.
// ---------------------------------------------------------------------------

__device__ __half g_flatH[1024 * 2048];
__device__ float g_graw4[4 * 1024 * 256];
__device__ __half g_gH[1024 * 256];
__device__ __half g_hrH[1024 * 4096];
__device__ float g_WtcR[32 * 1024];
__device__ __half g_WgcH[256 * 2048];
__device__ __half g_WheadsH[16 * 256 * 256];
__device__ __half g_WlogitH[4096 * 256];

__device__ __forceinline__ float round_tf32(float x) {
    float y;
    asm("cvt.rna.tf32.f32 %0, %1;" : "=f"(y) : "f"(x));
    return y;
}
__device__ __forceinline__ uint32_t as_tf32_bits(uint32_t bits) {
    float y;
    asm("cvt.rna.tf32.f32 %0, %1;" : "=f"(y) : "f"(__uint_as_float(bits)));
    return __float_as_uint(y);
}

__device__ __forceinline__ void mma_tf32(float* d, const uint32_t* a, const uint32_t* b) {
    asm volatile(
        "mma.sync.aligned.m16n8k8.row.col.f32.tf32.tf32.f32 "
        "{%0,%1,%2,%3},{%4,%5,%6,%7},{%8,%9},{%0,%1,%2,%3};"
        : "+f"(d[0]), "+f"(d[1]), "+f"(d[2]), "+f"(d[3])
        : "r"(a[0]), "r"(a[1]), "r"(a[2]), "r"(a[3]), "r"(b[0]), "r"(b[1]));
}
__device__ __forceinline__ void mma_f16(float* d, const uint32_t* a, uint32_t b0,
                                        uint32_t b1) {
    asm volatile(
        "mma.sync.aligned.m16n8k16.row.col.f32.f16.f16.f32 "
        "{%0,%1,%2,%3},{%4,%5,%6,%7},{%8,%9},{%0,%1,%2,%3};"
        : "+f"(d[0]), "+f"(d[1]), "+f"(d[2]), "+f"(d[3])
        : "r"(a[0]), "r"(a[1]), "r"(a[2]), "r"(a[3]), "r"(b0), "r"(b1));
}

__device__ __forceinline__ void ldsm_x4(uint32_t* r, uint32_t addr) {
    asm volatile(
        "ldmatrix.sync.aligned.m8n8.x4.shared.b16 {%0,%1,%2,%3}, [%4];"
        : "=r"(r[0]), "=r"(r[1]), "=r"(r[2]), "=r"(r[3])
        : "r"(addr));
}

__device__ __forceinline__ void cp16(uint32_t saddr, const void* gptr) {
    asm volatile("cp.async.cg.shared.global [%0], [%1], 16;" ::"r"(saddr), "l"(gptr));
}
__device__ __forceinline__ void cp_commit() { asm volatile("cp.async.commit_group;"); }
__device__ __forceinline__ uint32_t smem_u32(const void* p) {
    return (uint32_t)__cvta_generic_to_shared(p);
}

// ================ fp16 LDSM GEMM (stages B, C, D) — occupancy 2 =============
// C[.,N] = A @ B^T over K-extent Kext (halves), row stride lda (halves).
// blockIdx.z = split-K chunk. A,B fp16; fp32 accum. STAGES in {2,3}.
template <int BM, int BN, int BK, int WARPS_M, int WARPS_N, int STAGES, bool OUT_HALF>
__global__ void __launch_bounds__(256, 2)
    gemm_h16(const __half* __restrict__ A, const __half* __restrict__ B, void* Cv,
             int N, int Kext, int lda, long csplit) {
    static_assert(WARPS_M * WARPS_N == 8, "8 warps");
    constexpr int WM_ITER = BM / (WARPS_M * 16);
    constexpr int WN_PAIRS = BN / (WARPS_N * 16);
    static_assert(WM_ITER * WN_PAIRS * 2 * 4 <= 64, "acc fits 128-reg cap");
    constexpr int LDR = BK + 8;              // halves; 144B rows: conflict-free
    constexpr int ASZB = BM * LDR * 2;       // bytes
    constexpr int BSZB = BN * LDR * 2;
    constexpr int SSZB = ASZB + BSZB;
    constexpr int A_LD = BM * (BK / 8) / 256;
    constexpr int B_LD = BN * (BK / 8) / 256;
    static_assert(A_LD * 256 * 8 == BM * BK, "A chunks");
    static_assert(B_LD * 256 * 8 == BN * BK, "B chunks");

    extern __shared__ char smemc[];
    const uint32_t sbase = smem_u32(smemc);

    const int tid = threadIdx.x;
    const int warp = tid >> 5;
    const int lane = tid & 31;
    const int gid = lane >> 2;
    const int tig = lane & 3;
    const int wm0 = (warp / WARPS_N) * (WM_ITER * 16);
    const int wn0 = (warp % WARPS_N) * (WN_PAIRS * 16);
    const long brow = (long)blockIdx.y * BM;
    const long bcol = (long)blockIdx.x * BN;
    const int NK = Kext / BK;

    const __half* Ap = A + (long)blockIdx.z * Kext;
    const __half* Bp = B + (long)blockIdx.z * Kext;

    // ldmatrix lane offsets: lanes 0-15 -> rows 0-15 (k lo 8), 16-31 -> k hi 8.
    const int rowOff = lane & 15;
    const int colOff = (lane >> 4) * 8;
    const uint32_t aLane = 2u * ((wm0 + rowOff) * LDR + colOff);
    const uint32_t bLane = 2u * ((wn0 + rowOff) * LDR + colOff);

    auto issue_tile = [&](int kt) {
        const uint32_t st = sbase + (uint32_t)(kt % STAGES) * SSZB;
        const int k0 = kt * BK;
#pragma unroll
        for (int i = 0; i < A_LD; i++) {
            int idx = tid + i * 256;
            int r = idx / (BK / 8), c = idx % (BK / 8);
            cp16(st + 2u * (r * LDR) + c * 16u, Ap + (brow + r) * lda + k0 + c * 8);
        }
#pragma unroll
        for (int i = 0; i < B_LD; i++) {
            int idx = tid + i * 256;
            int r = idx / (BK / 8), c = idx % (BK / 8);
            cp16(st + ASZB + 2u * (r * LDR) + c * 16u,
                 Bp + (bcol + r) * lda + k0 + c * 8);
        }
        cp_commit();
    };

    float acc[WM_ITER][2 * WN_PAIRS][4];
#pragma unroll
    for (int i = 0; i < WM_ITER; i++)
#pragma unroll
        for (int j = 0; j < 2 * WN_PAIRS; j++)
#pragma unroll
            for (int t = 0; t < 4; t++) acc[i][j][t] = 0.0f;

    issue_tile(0);
    if (STAGES == 3 && NK > 1) issue_tile(1);

    for (int kt = 0; kt < NK; kt++) {
        if (STAGES == 3) {
            // Steady state: allow newest load (kt+1) to stay in flight.
            if (kt + 1 < NK)
                asm volatile("cp.async.wait_group 1;" ::: "memory");
            else
                asm volatile("cp.async.wait_group 0;" ::: "memory");
            __syncthreads();
            if (kt + 2 < NK) issue_tile(kt + 2);
        } else {
            asm volatile("cp.async.wait_group 0;" ::: "memory");
            __syncthreads();
            if (kt + 1 < NK) issue_tile(kt + 1);
        }

        const uint32_t st = sbase + (uint32_t)(kt % STAGES) * SSZB;
        const uint32_t aBase = st + aLane;
        const uint32_t bBase = st + ASZB + bLane;

#pragma unroll
        for (int ks = 0; ks < BK / 16; ks++) {
            uint32_t af[WM_ITER][4];
            uint32_t bq[WN_PAIRS][4];
#pragma unroll
            for (int i = 0; i < WM_ITER; i++)
                ldsm_x4(af[i], aBase + 2u * (i * 16 * LDR) + ks * 32u);
#pragma unroll
            for (int p = 0; p < WN_PAIRS; p++)
                ldsm_x4(bq[p], bBase + 2u * (p * 16 * LDR) + ks * 32u);
#pragma unroll
            for (int i = 0; i < WM_ITER; i++)
#pragma unroll
                for (int p = 0; p < WN_PAIRS; p++) {
                    mma_f16(acc[i][2 * p], af[i], bq[p][0], bq[p][2]);
                    mma_f16(acc[i][2 * p + 1], af[i], bq[p][1], bq[p][3]);
                }
        }
    }

    // Epilogue: acc[i][2p+h] -> rows (wm0+i*16+gid, +8),
    //           cols bcol+wn0+p*16+h*8+tig*2 (+1).
#pragma unroll
    for (int i = 0; i < WM_ITER; i++) {
#pragma unroll
        for (int p = 0; p < WN_PAIRS; p++) {
#pragma unroll
            for (int h = 0; h < 2; h++) {
                const float* a4 = acc[i][2 * p + h];
                long r = brow + wm0 + i * 16 + gid;
                long c = bcol + wn0 + p * 16 + h * 8 + tig * 2;
                if (OUT_HALF) {
                    __half* Ch = (__half*)Cv;
                    *reinterpret_cast<__half2*>(Ch + r * N + c) =
                        __floats2half2_rn(a4[0], a4[1]);
                    *reinterpret_cast<__half2*>(Ch + (r + 8) * N + c) =
                        __floats2half2_rn(a4[2], a4[3]);
                } else {
                    float* Cf = (float*)Cv + (long)blockIdx.z * csplit;
                    *reinterpret_cast<float2*>(Cf + r * N + c) =
                        make_float2(a4[0], a4[1]);
                    *reinterpret_cast<float2*>(Cf + (r + 8) * N + c) =
                        make_float2(a4[2], a4[3]);
                }
            }
        }
    }
}

// ========== Stage A: tf32 LDSM GEMM, fp16 output (r9-validated layout) =======
// flatH[M,32] = x[M,1024] @ W_tcR[32,1024]^T. BM=128, BN=32, BK=64 floats,
// warps 8x1 (warp tile 16x32), 2-stage, CVT post-ldmatrix, occ 2.
__global__ void __launch_bounds__(256, 2)
    gemm_a_tf32(const float* __restrict__ A, const float* __restrict__ B,
                __half* __restrict__ C, int K) {
    constexpr int BM = 128, BN = 32, BK = 64;
    constexpr int LDR = BK + 4;              // 68 floats
    constexpr int ASZB = BM * LDR * 4;       // 34,816
    constexpr int BSZB = BN * LDR * 4;       // 8,704
    constexpr int SSZB = ASZB + BSZB;        // 43,520

    extern __shared__ char smemc[];
    const uint32_t sbase = smem_u32(smemc);

    const int tid = threadIdx.x;
    const int warp = tid >> 5;
    const int lane = tid & 31;
    const int gid = lane >> 2;
    const int tig = lane & 3;
    const int wm0 = warp * 16;
    const long brow = (long)blockIdx.y * BM;
    const int NK = K / BK;

    // fp32-as-b16x2 ldmatrix lane offsets (validated round 8/9).
    const int rowOffA = (lane & 7) + ((lane >> 3) & 1) * 8;
    const int colOffA = (lane >> 4) * 4;
    const int rowOffB = (lane & 7) + (lane >> 4) * 8;
    const int colOffB = ((lane >> 3) & 1) * 4;
    const uint32_t aLane = 4u * ((wm0 + rowOffA) * LDR + colOffA);
    const uint32_t bLane = 4u * (rowOffB * LDR + colOffB);

    auto issue_tile = [&](int kt) {
        const uint32_t st = sbase + (uint32_t)(kt & 1) * SSZB;
        const int k0 = kt * BK;
        // A: 128 rows x 16 chunks = 2048, 8 per thread.
#pragma unroll
        for (int i = 0; i < 8; i++) {
            int idx = tid + i * 256;
            int r = idx >> 4, c = idx & 15;
            cp16(st + 4u * (r * LDR + c * 4), A + (brow + r) * K + k0 + c * 4);
        }
        // B: 32 rows x 16 chunks = 512, 2 per thread.
#pragma unroll
        for (int i = 0; i < 2; i++) {
            int idx = tid + i * 256;
            int r = idx >> 4, c = idx & 15;
            cp16(st + ASZB + 4u * (r * LDR + c * 4), B + r * K + k0 + c * 4);
        }
        cp_commit();
    };

    float acc[4][4];
#pragma unroll
    for (int j = 0; j < 4; j++)
#pragma unroll
        for (int t = 0; t < 4; t++) acc[j][t] = 0.0f;

    issue_tile(0);
    asm volatile("cp.async.wait_group 0;" ::: "memory");
    __syncthreads();

    for (int kt = 0; kt < NK; kt++) {
        if (kt + 1 < NK) issue_tile(kt + 1);

        const uint32_t st = sbase + (uint32_t)(kt & 1) * SSZB;
        const uint32_t aBase = st + aLane;
        const uint32_t bBase = st + ASZB + bLane;

#pragma unroll
        for (int ks = 0; ks < BK / 8; ks++) {
            uint32_t af[4];
            uint32_t bq0[4], bq1[4];
            ldsm_x4(af, aBase + ks * 32u);
#pragma unroll
            for (int t = 0; t < 4; t++) af[t] = as_tf32_bits(af[t]);
            ldsm_x4(bq0, bBase + ks * 32u);
            ldsm_x4(bq1, bBase + 4u * (16 * LDR) + ks * 32u);
            mma_tf32(acc[0], af, &bq0[0]);
            mma_tf32(acc[1], af, &bq0[2]);
            mma_tf32(acc[2], af, &bq1[0]);
            mma_tf32(acc[3], af, &bq1[2]);
        }

        if (kt + 1 < NK) asm volatile("cp.async.wait_group 0;" ::: "memory");
        __syncthreads();
    }

    // Epilogue: acc[j] -> rows (wm0+gid, +8), cols j*8+tig*2 (+1). N=32, fp16.
#pragma unroll
    for (int j = 0; j < 4; j++) {
        long r = brow + wm0 + gid;
        long c = j * 8 + tig * 2;
        *reinterpret_cast<__half2*>(C + r * 32 + c) =
            __floats2half2_rn(acc[j][0], acc[j][1]);
        *reinterpret_cast<__half2*>(C + (r + 8) * 32 + c) =
            __floats2half2_rn(acc[j][2], acc[j][3]);
    }
}

// RMSNorm over 4 split-K partials; fp16 output.
__global__ void rmsnorm4_kernel(const float* __restrict__ gin,
                                const float* __restrict__ bias,
                                const float* __restrict__ scale,
                                __half* __restrict__ gout) {
    const int b = blockIdx.x;
    const int h = threadIdx.x;  // 256 threads
    const int idx = b * 256 + h;
    float v = gin[idx] + gin[262144 + idx];
    v += gin[2 * 262144 + idx];
    v += gin[3 * 262144 + idx];
    v += bias[h];
    float s = v * v;
#pragma unroll
    for (int o = 16; o > 0; o >>= 1) s += __shfl_xor_sync(0xFFFFFFFFu, s, o);
    __shared__ float ws[8];
    if ((h & 31) == 0) ws[h >> 5] = s;
    __syncthreads();
    float tot = 0.0f;
#pragma unroll
    for (int w = 0; w < 8; w++) tot += ws[w];
    float inv = rsqrtf(tot * (1.0f / 256.0f) + 1e-6f);
    gout[idx] = __float2half_rn(v * inv * scale[h]);
}

// Fused prep: W_tc -> tf32 fp32; W_gc/W_heads/W_logit -> fp16. float4-wide.
// Blocks: [0,32) tc | [32,544) gc | [544,1568) heads | [1568,2592) logit.
__global__ void prep_weights_kernel(const float* __restrict__ s0, float* d0,
                                    const float* __restrict__ s1, __half* d1,
                                    const float* __restrict__ s2, __half* d2,
                                    const float* __restrict__ s3, __half* d3) {
    const int blk = blockIdx.x;
    if (blk < 32) {
        int idx = blk * 256 + threadIdx.x;
        float4 v = reinterpret_cast<const float4*>(s0)[idx];
        v.x = round_tf32(v.x);
        v.y = round_tf32(v.y);
        v.z = round_tf32(v.z);
        v.w = round_tf32(v.w);
        reinterpret_cast<float4*>(d0)[idx] = v;
        return;
    }
    const float* src;
    __half* dst;
    int idx;
    if (blk < 544) {
        src = s1; dst = d1; idx = (blk - 32) * 256 + threadIdx.x;
    } else if (blk < 1568) {
        src = s2; dst = d2; idx = (blk - 544) * 256 + threadIdx.x;
    } else {
        src = s3; dst = d3; idx = (blk - 1568) * 256 + threadIdx.x;
    }
    float4 v = reinterpret_cast<const float4*>(src)[idx];
    reinterpret_cast<__half2*>(dst)[idx * 2 + 0] = __floats2half2_rn(v.x, v.y);
    reinterpret_cast<__half2*>(dst)[idx * 2 + 1] = __floats2half2_rn(v.z, v.w);
}

extern "C" void kernel_launch(void* const* d_in, const int* in_sizes, int n_in,
                              void* d_out, int out_size) {
    const float* x         = (const float*)d_in[0];  // (1024, 64, 1024)
    const float* W_tc      = (const float*)d_in[1];  // (32, 1024)
    const float* W_gc      = (const float*)d_in[2];  // (256, 2048)
    const float* b_gc      = (const float*)d_in[3];  // (256,)
    const float* rms_scale = (const float*)d_in[4];  // (256,)
    const float* W_heads   = (const float*)d_in[5];  // (16, 256, 256)
    const float* W_logit   = (const float*)d_in[6];  // (4096, 256)
    float* out = (float*)d_out;                      // (1024, 16, 64, 64)

    __half *flatH, *ggH, *hrH, *wgcH, *whH, *wlH;
    float *graw4, *wtcR;
    cudaGetSymbolAddress((void**)&flatH, g_flatH);
    cudaGetSymbolAddress((void**)&graw4, g_graw4);
    cudaGetSymbolAddress((void**)&ggH, g_gH);
    cudaGetSymbolAddress((void**)&hrH, g_hrH);
    cudaGetSymbolAddress((void**)&wtcR, g_WtcR);
    cudaGetSymbolAddress((void**)&wgcH, g_WgcH);
    cudaGetSymbolAddress((void**)&whH, g_WheadsH);
    cudaGetSymbolAddress((void**)&wlH, g_WlogitH);

    // Prep (2592 blocks).
    prep_weights_kernel<<<2592, 256>>>(W_tc, wtcR, W_gc, wgcH, W_heads, whH,
                                       W_logit, wlH);

    // Stage A: tf32 LDSM, BM=128/BN=32/BK=64, 2-stage, occ 2. smem 87,040 B.
    {
        size_t smem = 2 * ((size_t)(128 + 32) * 68 * 4);
        cudaFuncSetAttribute(gemm_a_tf32, cudaFuncAttributeMaxDynamicSharedMemorySize,
                             (int)smem);
        gemm_a_tf32<<<dim3(1, 512), 256, smem>>>(x, wtcR, flatH, 1024);
    }
    // Stage B: fp16, split-K x4, 3-stage. BM=64,BN=128,BK=64h; smem 82,944 B.
    {
        auto k = gemm_h16<64, 128, 64, 2, 4, 3, false>;
        size_t smem = 3 * (size_t)(64 + 128) * (64 + 8) * 2;
        cudaFuncSetAttribute(k, cudaFuncAttributeMaxDynamicSharedMemorySize, (int)smem);
        k<<<dim3(2, 16, 4), 256, smem>>>(flatH, wgcH, graw4, 256, 512, 2048,
                                         (long)1024 * 256);
    }
    rmsnorm4_kernel<<<1024, 256>>>(graw4, b_gc, rms_scale, ggH);

    // Stages C/D: fp16, BM=128,BN=128,BK=64h, 3-stage, occ 2. smem 110,592 B.
    {
        size_t smem = 3 * (size_t)(128 + 128) * (64 + 8) * 2;
        auto kc = gemm_h16<128, 128, 64, 2, 4, 3, true>;
        auto kd = gemm_h16<128, 128, 64, 2, 4, 3, false>;
        cudaFuncSetAttribute(kc, cudaFuncAttributeMaxDynamicSharedMemorySize, (int)smem);
        cudaFuncSetAttribute(kd, cudaFuncAttributeMaxDynamicSharedMemorySize, (int)smem);
        // C: M=1024, N=4096, K=256 -> grid (32, 8).
        kc<<<dim3(32, 8), 256, smem>>>(ggH, whH, hrH, 4096, 256, 256, 0);
        // D: M=16384, N=4096, K=256 -> grid (32, 128).
        kd<<<dim3(32, 128), 256, smem>>>(hrH, wlH, out, 4096, 256, 256, 0);
    }
}